// round 7
// baseline (speedup 1.0000x reference)
#include <cuda_runtime.h>
#include <math.h>

// Problem constants
#define BB   8
#define LL   2048
#define DD   1024
#define TOK  (BB*LL)            // 16384
#define SROWS 2049              // S_max + 1

// ---------------- scratch (no allocations allowed) ----------------
__device__ float g_partial[8 * TOK];   // per col-group partial logits
__device__ int   g_hard[TOK];          // hard boundary 0/1
__device__ int   g_cum[TOK];           // inclusive cumsum of hard
__device__ int   g_start[BB * 2050];   // segment start indices per row
__device__ int   g_nseg[BB];           // number of non-empty segments per row

// ---------------- f32x2 helpers (Blackwell packed fp32) ----------------
__device__ __forceinline__ unsigned long long dupf(float v) {
    unsigned long long r;
    asm("mov.b64 %0, {%1, %1};" : "=l"(r) : "f"(v));
    return r;
}
__device__ __forceinline__ void ffma2(unsigned long long& acc,
                                      unsigned long long a,
                                      unsigned long long b) {
    asm("fma.rn.f32x2 %0, %1, %2, %0;" : "+l"(acc) : "l"(a), "l"(b));
}
__device__ __forceinline__ float2 unpack2(unsigned long long v) {
    float2 f;
    asm("mov.b64 {%0, %1}, %2;" : "=f"(f.x), "=f"(f.y) : "l"(v));
    return f;
}

// ---------------------------------------------------------------------
// Kernel 1: fused GEMM  partial[cg][t] = sum_{j in colgrp} relu(x@W1 + b1)[t,j] * W2[j]
// grid (128 token tiles, 8 col groups), 256 threads, 128x128 tile, K-chunk 16.
// ---------------------------------------------------------------------
__global__ __launch_bounds__(256, 2)
void gemm_logits_kernel(const float* __restrict__ x,
                        const float* __restrict__ W1,
                        const float* __restrict__ b1,
                        const float* __restrict__ W2) {
    __shared__ float As[16][132];   // transposed A tile (padded)
    __shared__ float Bs[16][128];
    __shared__ float b1s[128];
    __shared__ float w2s[128];

    const int tid = threadIdx.x;
    const int t0  = blockIdx.x * 128;
    const int j0  = blockIdx.y * 128;
    const int tx  = tid & 15;
    const int ty  = tid >> 4;
    const int row_base = ty * 8;
    const int col_base = tx * 8;

    if (tid < 128) { b1s[tid] = b1[j0 + tid]; w2s[tid] = W2[j0 + tid]; }

    // global load mapping
    const int ar0 = tid >> 2;          // token row within tile (0..63)
    const int akp = tid & 3;           // k float4 slot (0..3)
    const float* aP = x + (size_t)(t0 + ar0) * DD + akp * 4;
    const int bk0 = tid >> 5;          // k row (0..7)
    const int bj  = (tid & 31) * 4;    // col offset
    const float* bP = W1 + (size_t)bk0 * DD + j0 + bj;

    unsigned long long acc[8][4];
#pragma unroll
    for (int i = 0; i < 8; ++i)
#pragma unroll
        for (int p = 0; p < 4; ++p) acc[i][p] = 0ull;

    // prefetch + store chunk 0
    float4 aR0 = *(const float4*)(aP);
    float4 aR1 = *(const float4*)(aP + 64 * DD);
    float4 bR0 = *(const float4*)(bP);
    float4 bR1 = *(const float4*)(bP + 8 * DD);

    {
        const int kb = akp * 4;
        As[kb + 0][ar0] = aR0.x; As[kb + 1][ar0] = aR0.y;
        As[kb + 2][ar0] = aR0.z; As[kb + 3][ar0] = aR0.w;
        As[kb + 0][ar0 + 64] = aR1.x; As[kb + 1][ar0 + 64] = aR1.y;
        As[kb + 2][ar0 + 64] = aR1.z; As[kb + 3][ar0 + 64] = aR1.w;
        *(float4*)&Bs[bk0][bj]     = bR0;
        *(float4*)&Bs[bk0 + 8][bj] = bR1;
    }
    __syncthreads();

    for (int kc = 0; kc < 64; ++kc) {
        if (kc < 63) {
            const int kn = (kc + 1) * 16;
            aR0 = *(const float4*)(aP + kn);
            aR1 = *(const float4*)(aP + 64 * DD + kn);
            bR0 = *(const float4*)(bP + (size_t)kn * DD);
            bR1 = *(const float4*)(bP + (size_t)(kn + 8) * DD);
        }
#pragma unroll
        for (int kk = 0; kk < 16; ++kk) {
            float4 a01 = *(const float4*)&As[kk][row_base];
            float4 a23 = *(const float4*)&As[kk][row_base + 4];
            ulonglong2 bb0 = *(const ulonglong2*)&Bs[kk][col_base];
            ulonglong2 bb1 = *(const ulonglong2*)&Bs[kk][col_base + 4];
            unsigned long long B2[4] = { bb0.x, bb0.y, bb1.x, bb1.y };
            float av[8] = { a01.x, a01.y, a01.z, a01.w,
                            a23.x, a23.y, a23.z, a23.w };
#pragma unroll
            for (int i = 0; i < 8; ++i) {
                unsigned long long a2 = dupf(av[i]);
#pragma unroll
                for (int p = 0; p < 4; ++p) ffma2(acc[i][p], a2, B2[p]);
            }
        }
        if (kc < 63) {
            __syncthreads();
            const int kb = akp * 4;
            As[kb + 0][ar0] = aR0.x; As[kb + 1][ar0] = aR0.y;
            As[kb + 2][ar0] = aR0.z; As[kb + 3][ar0] = aR0.w;
            As[kb + 0][ar0 + 64] = aR1.x; As[kb + 1][ar0 + 64] = aR1.y;
            As[kb + 2][ar0 + 64] = aR1.z; As[kb + 3][ar0 + 64] = aR1.w;
            *(float4*)&Bs[bk0][bj]     = bR0;
            *(float4*)&Bs[bk0 + 8][bj] = bR1;
            __syncthreads();
        }
    }

    __syncthreads();  // done reading As/Bs; reuse As as reduction buffer

    // epilogue: relu + dot with W2, per-thread partial over its 8 cols
    float lg[8];
#pragma unroll
    for (int i = 0; i < 8; ++i) lg[i] = 0.0f;
#pragma unroll
    for (int i = 0; i < 8; ++i) {
#pragma unroll
        for (int p = 0; p < 4; ++p) {
            float2 c = unpack2(acc[i][p]);
            const int jc = col_base + p * 2;
            float h0 = fmaxf(c.x + b1s[jc], 0.0f);
            float h1 = fmaxf(c.y + b1s[jc + 1], 0.0f);
            lg[i] += h0 * w2s[jc] + h1 * w2s[jc + 1];
        }
    }

    float* red = &As[0][0];  // 128*16 = 2048 <= 16*132
#pragma unroll
    for (int i = 0; i < 8; ++i) red[(row_base + i) * 16 + tx] = lg[i];
    __syncthreads();

    if (tid < 128) {
        float s = 0.0f;
#pragma unroll
        for (int t = 0; t < 16; ++t) s += red[tid * 16 + t];
        g_partial[(size_t)blockIdx.y * TOK + t0 + tid] = s;
    }
}

// ---------------------------------------------------------------------
// Kernel 2: combine partials + gumbel noise -> hard boundaries
// ---------------------------------------------------------------------
__global__ void boundary_kernel(const float* __restrict__ noise,
                                const float* __restrict__ b2) {
    const int i = blockIdx.x * 256 + threadIdx.x;
    float s = b2[0];
#pragma unroll
    for (int cg = 0; cg < 8; ++cg) s += g_partial[cg * TOK + i];
    float u = noise[i];
    u = fminf(fmaxf(u, 1e-6f), 1.0f - 1e-6f);
    float z = s + logf(u) - log1pf(-u);
    float soft = 1.0f / (1.0f + expf(-z));
    g_hard[i] = (soft > 0.5f) ? 1 : 0;
}

// ---------------------------------------------------------------------
// Kernel 3: per-row prefix scan, segment starts, inclusive cumsum
// one block per batch row, 256 threads x 8 elements
// ---------------------------------------------------------------------
__global__ void scan_kernel() {
    const int b = blockIdx.x;
    const int tid = threadIdx.x;
    __shared__ int e_sh[LL];
    __shared__ int ts[256];

    const int base = tid * 8;
    int h[8];
    int sum = 0;
#pragma unroll
    for (int j = 0; j < 8; ++j) { h[j] = g_hard[b * LL + base + j]; sum += h[j]; }
    ts[tid] = sum;
    __syncthreads();

    // inclusive Hillis-Steele scan over 256 thread sums
    for (int off = 1; off < 256; off <<= 1) {
        int v = (tid >= off) ? ts[tid - off] : 0;
        __syncthreads();
        ts[tid] += v;
        __syncthreads();
    }
    int run = ts[tid] - sum;  // exclusive base for this chunk

#pragma unroll
    for (int j = 0; j < 8; ++j) {
        e_sh[base + j] = run;                       // exclusive prefix (segment id, downsample)
        g_cum[b * LL + base + j] = run + h[j];      // inclusive cumsum (upsample gather idx)
        run += h[j];
    }
    __syncthreads();

#pragma unroll
    for (int j = 0; j < 8; ++j) {
        const int l = base + j;
        const int el = e_sh[l];
        if (l == 0 || e_sh[l - 1] != el) g_start[b * 2050 + el] = l;
    }
    if (tid == 255) {
        const int ns = e_sh[LL - 1] + 1;
        g_nseg[b] = ns;
        g_start[b * 2050 + ns] = LL;  // sentinel end
    }
}

// ---------------------------------------------------------------------
// Kernel 4: shortened = [null_group ; segment means ; zeros]
// grid (2049, 8), 256 threads -> one float4 per thread
// ---------------------------------------------------------------------
__global__ void shortened_kernel(const float* __restrict__ x,
                                 const float* __restrict__ null_group,
                                 float* __restrict__ outS) {
    const int b = blockIdx.y;
    const int srow = blockIdx.x;
    const int tid = threadIdx.x;
    float4* op = (float4*)(outS + ((size_t)b * SROWS + srow) * DD) + tid;

    if (srow == 0) { *op = ((const float4*)null_group)[tid]; return; }
    const int s = srow - 1;
    if (s >= g_nseg[b]) { *op = make_float4(0.f, 0.f, 0.f, 0.f); return; }

    const int l0 = g_start[b * 2050 + s];
    const int l1 = g_start[b * 2050 + s + 1];
    float4 acc = make_float4(0.f, 0.f, 0.f, 0.f);
    const float4* xp = (const float4*)(x + ((size_t)b * LL + l0) * DD) + tid;
    for (int l = l0; l < l1; ++l) {
        float4 v = *xp;
        acc.x += v.x; acc.y += v.y; acc.z += v.z; acc.w += v.w;
        xp += DD / 4;
    }
    const float inv = 1.0f / ((float)(l1 - l0) + 1e-9f);
    acc.x *= inv; acc.y *= inv; acc.z *= inv; acc.w *= inv;
    *op = acc;
}

// ---------------------------------------------------------------------
// Kernel 5: upsampled[b,l,:] = shortened[b, cumsum(l), :]   (scale == 1.0f exactly)
// ---------------------------------------------------------------------
__global__ void upsample_kernel(const float* __restrict__ outS,
                                float* __restrict__ outU) {
    const int b = blockIdx.y;
    const int l = blockIdx.x;
    const int tid = threadIdx.x;
    const int c = g_cum[b * LL + l];
    const float4* sp = (const float4*)(outS + ((size_t)b * SROWS + c) * DD) + tid;
    float4* up = (float4*)(outU + ((size_t)b * LL + l) * DD) + tid;
    *up = *sp;
}

// ---------------------------------------------------------------------
// Kernel 6: binomial consistency loss (scalar)
// ---------------------------------------------------------------------
__global__ void loss_kernel(float* __restrict__ outLoss) {
    if (threadIdx.x == 0) {
        const double Lf = 2048.0;
        const double lgL = lgamma(2049.0);
        const double lp = log(0.25);
        const double l1p = log(0.75);
        double s = 0.0;
        for (int b = 0; b < BB; ++b) {
            double k = (double)g_cum[b * LL + LL - 1];
            double logp = lgL - lgamma(k + 1.0) - lgamma(Lf - k + 1.0)
                        + k * lp + (Lf - k) * l1p;
            s += logp;
        }
        outLoss[0] = (float)(-(s / 8.0) / 2048.0);
    }
}

// ---------------------------------------------------------------------
extern "C" void kernel_launch(void* const* d_in, const int* in_sizes, int n_in,
                              void* d_out, int out_size) {
    (void)in_sizes; (void)n_in; (void)out_size;

    const float* x          = (const float*)d_in[0];
    const float* noise      = (const float*)d_in[1];
    const float* W1         = (const float*)d_in[2];
    const float* b1         = (const float*)d_in[3];
    const float* W2         = (const float*)d_in[4];
    const float* b2         = (const float*)d_in[5];
    const float* null_group = (const float*)d_in[6];

    float* out  = (float*)d_out;
    float* outS = out;                                     // [8, 2049, 1024]
    float* outU = outS + (size_t)BB * SROWS * DD;          // [8, 2048, 1024]
    float* outL = outU + (size_t)BB * LL * DD;             // scalar

    gemm_logits_kernel<<<dim3(TOK / 128, DD / 128), 256>>>(x, W1, b1, W2);
    boundary_kernel<<<TOK / 256, 256>>>(noise, b2);
    scan_kernel<<<BB, 256>>>();
    shortened_kernel<<<dim3(SROWS, BB), 256>>>(x, null_group, outS);
    upsample_kernel<<<dim3(LL, BB), 256>>>(outS, outU);
    loss_kernel<<<1, 32>>>(outL);
}

// round 8
// speedup vs baseline: 1.0021x; 1.0021x over previous
#include <cuda_runtime.h>
#include <math.h>

// Problem constants
#define BB   8
#define LL   2048
#define DD   1024
#define TOK  (BB*LL)            // 16384
#define SROWS 2049              // S_max + 1

// ---------------- scratch (no allocations allowed) ----------------
__device__ float g_partial[8 * TOK];   // per col-group partial logits
__device__ int   g_hard[TOK];          // hard boundary 0/1
__device__ int   g_cum[TOK];           // inclusive cumsum of hard
__device__ int   g_start[BB * 2050];   // segment start indices per row
__device__ int   g_nseg[BB];           // number of non-empty segments per row

// ---------------- f32x2 helpers (Blackwell packed fp32) ----------------
__device__ __forceinline__ unsigned long long dupf(float v) {
    unsigned long long r;
    asm("mov.b64 %0, {%1, %1};" : "=l"(r) : "f"(v));
    return r;
}
__device__ __forceinline__ void ffma2(unsigned long long& acc,
                                      unsigned long long a,
                                      unsigned long long b) {
    asm("fma.rn.f32x2 %0, %1, %2, %0;" : "+l"(acc) : "l"(a), "l"(b));
}
__device__ __forceinline__ float2 unpack2(unsigned long long v) {
    float2 f;
    asm("mov.b64 {%0, %1}, %2;" : "=f"(f.x), "=f"(f.y) : "l"(v));
    return f;
}

// ---------------------------------------------------------------------
// Kernel 1: fused GEMM  partial[cg][t] = sum_{j in colgrp} relu(x@W1 + b1)[t,j] * W2[j]
// grid (128 token tiles, 8 col groups), 256 threads, 128x128 tile, K-chunk 16.
// ---------------------------------------------------------------------
__global__ __launch_bounds__(256, 2)
void gemm_logits_kernel(const float* __restrict__ x,
                        const float* __restrict__ W1,
                        const float* __restrict__ b1,
                        const float* __restrict__ W2) {
    __shared__ float As[16][132];   // transposed A tile (padded)
    __shared__ float Bs[16][128];
    __shared__ float b1s[128];
    __shared__ float w2s[128];

    const int tid = threadIdx.x;
    const int t0  = blockIdx.x * 128;
    const int j0  = blockIdx.y * 128;
    const int tx  = tid & 15;
    const int ty  = tid >> 4;
    const int row_base = ty * 8;
    const int col_base = tx * 8;

    if (tid < 128) { b1s[tid] = b1[j0 + tid]; w2s[tid] = W2[j0 + tid]; }

    // global load mapping
    const int ar0 = tid >> 2;          // token row within tile (0..63)
    const int akp = tid & 3;           // k float4 slot (0..3)
    const float* aP = x + (size_t)(t0 + ar0) * DD + akp * 4;
    const int bk0 = tid >> 5;          // k row (0..7)
    const int bj  = (tid & 31) * 4;    // col offset
    const float* bP = W1 + (size_t)bk0 * DD + j0 + bj;

    unsigned long long acc[8][4];
#pragma unroll
    for (int i = 0; i < 8; ++i)
#pragma unroll
        for (int p = 0; p < 4; ++p) acc[i][p] = 0ull;

    // prefetch + store chunk 0
    float4 aR0 = *(const float4*)(aP);
    float4 aR1 = *(const float4*)(aP + 64 * DD);
    float4 bR0 = *(const float4*)(bP);
    float4 bR1 = *(const float4*)(bP + 8 * DD);

    {
        const int kb = akp * 4;
        As[kb + 0][ar0] = aR0.x; As[kb + 1][ar0] = aR0.y;
        As[kb + 2][ar0] = aR0.z; As[kb + 3][ar0] = aR0.w;
        As[kb + 0][ar0 + 64] = aR1.x; As[kb + 1][ar0 + 64] = aR1.y;
        As[kb + 2][ar0 + 64] = aR1.z; As[kb + 3][ar0 + 64] = aR1.w;
        *(float4*)&Bs[bk0][bj]     = bR0;
        *(float4*)&Bs[bk0 + 8][bj] = bR1;
    }
    __syncthreads();

    for (int kc = 0; kc < 64; ++kc) {
        if (kc < 63) {
            const int kn = (kc + 1) * 16;
            aR0 = *(const float4*)(aP + kn);
            aR1 = *(const float4*)(aP + 64 * DD + kn);
            bR0 = *(const float4*)(bP + (size_t)kn * DD);
            bR1 = *(const float4*)(bP + (size_t)(kn + 8) * DD);
        }
#pragma unroll
        for (int kk = 0; kk < 16; ++kk) {
            float4 a01 = *(const float4*)&As[kk][row_base];
            float4 a23 = *(const float4*)&As[kk][row_base + 4];
            ulonglong2 bb0 = *(const ulonglong2*)&Bs[kk][col_base];
            ulonglong2 bb1 = *(const ulonglong2*)&Bs[kk][col_base + 4];
            unsigned long long B2[4] = { bb0.x, bb0.y, bb1.x, bb1.y };
            float av[8] = { a01.x, a01.y, a01.z, a01.w,
                            a23.x, a23.y, a23.z, a23.w };
#pragma unroll
            for (int i = 0; i < 8; ++i) {
                unsigned long long a2 = dupf(av[i]);
#pragma unroll
                for (int p = 0; p < 4; ++p) ffma2(acc[i][p], a2, B2[p]);
            }
        }
        if (kc < 63) {
            __syncthreads();
            const int kb = akp * 4;
            As[kb + 0][ar0] = aR0.x; As[kb + 1][ar0] = aR0.y;
            As[kb + 2][ar0] = aR0.z; As[kb + 3][ar0] = aR0.w;
            As[kb + 0][ar0 + 64] = aR1.x; As[kb + 1][ar0 + 64] = aR1.y;
            As[kb + 2][ar0 + 64] = aR1.z; As[kb + 3][ar0 + 64] = aR1.w;
            *(float4*)&Bs[bk0][bj]     = bR0;
            *(float4*)&Bs[bk0 + 8][bj] = bR1;
            __syncthreads();
        }
    }

    __syncthreads();  // done reading As/Bs; reuse As as reduction buffer

    // epilogue: relu + dot with W2, per-thread partial over its 8 cols
    float lg[8];
#pragma unroll
    for (int i = 0; i < 8; ++i) lg[i] = 0.0f;
#pragma unroll
    for (int i = 0; i < 8; ++i) {
#pragma unroll
        for (int p = 0; p < 4; ++p) {
            float2 c = unpack2(acc[i][p]);
            const int jc = col_base + p * 2;
            float h0 = fmaxf(c.x + b1s[jc], 0.0f);
            float h1 = fmaxf(c.y + b1s[jc + 1], 0.0f);
            lg[i] += h0 * w2s[jc] + h1 * w2s[jc + 1];
        }
    }

    float* red = &As[0][0];  // 128*16 = 2048 <= 16*132
#pragma unroll
    for (int i = 0; i < 8; ++i) red[(row_base + i) * 16 + tx] = lg[i];
    __syncthreads();

    if (tid < 128) {
        float s = 0.0f;
#pragma unroll
        for (int t = 0; t < 16; ++t) s += red[tid * 16 + t];
        g_partial[(size_t)blockIdx.y * TOK + t0 + tid] = s;
    }
}

// ---------------------------------------------------------------------
// Kernel 2: combine partials + gumbel noise -> hard boundaries
// ---------------------------------------------------------------------
__global__ void boundary_kernel(const float* __restrict__ noise,
                                const float* __restrict__ b2) {
    const int i = blockIdx.x * 256 + threadIdx.x;
    float s = b2[0];
#pragma unroll
    for (int cg = 0; cg < 8; ++cg) s += g_partial[cg * TOK + i];
    float u = noise[i];
    u = fminf(fmaxf(u, 1e-6f), 1.0f - 1e-6f);
    float z = s + logf(u) - log1pf(-u);
    float soft = 1.0f / (1.0f + expf(-z));
    g_hard[i] = (soft > 0.5f) ? 1 : 0;
}

// ---------------------------------------------------------------------
// Kernel 3: per-row prefix scan, segment starts, inclusive cumsum
// one block per batch row, 256 threads x 8 elements
// ---------------------------------------------------------------------
__global__ void scan_kernel() {
    const int b = blockIdx.x;
    const int tid = threadIdx.x;
    __shared__ int e_sh[LL];
    __shared__ int ts[256];

    const int base = tid * 8;
    int h[8];
    int sum = 0;
#pragma unroll
    for (int j = 0; j < 8; ++j) { h[j] = g_hard[b * LL + base + j]; sum += h[j]; }
    ts[tid] = sum;
    __syncthreads();

    // inclusive Hillis-Steele scan over 256 thread sums
    for (int off = 1; off < 256; off <<= 1) {
        int v = (tid >= off) ? ts[tid - off] : 0;
        __syncthreads();
        ts[tid] += v;
        __syncthreads();
    }
    int run = ts[tid] - sum;  // exclusive base for this chunk

#pragma unroll
    for (int j = 0; j < 8; ++j) {
        e_sh[base + j] = run;                       // exclusive prefix (segment id, downsample)
        g_cum[b * LL + base + j] = run + h[j];      // inclusive cumsum (upsample gather idx)
        run += h[j];
    }
    __syncthreads();

#pragma unroll
    for (int j = 0; j < 8; ++j) {
        const int l = base + j;
        const int el = e_sh[l];
        if (l == 0 || e_sh[l - 1] != el) g_start[b * 2050 + el] = l;
    }
    if (tid == 255) {
        const int ns = e_sh[LL - 1] + 1;
        g_nseg[b] = ns;
        g_start[b * 2050 + ns] = LL;  // sentinel end
    }
}

// ---------------------------------------------------------------------
// Kernel 4: shortened = [null_group ; segment means ; zeros]
// grid (2049, 8), 256 threads -> one float4 per thread
// ---------------------------------------------------------------------
__global__ void shortened_kernel(const float* __restrict__ x,
                                 const float* __restrict__ null_group,
                                 float* __restrict__ outS) {
    const int b = blockIdx.y;
    const int srow = blockIdx.x;
    const int tid = threadIdx.x;
    float4* op = (float4*)(outS + ((size_t)b * SROWS + srow) * DD) + tid;

    if (srow == 0) { *op = ((const float4*)null_group)[tid]; return; }
    const int s = srow - 1;
    if (s >= g_nseg[b]) { *op = make_float4(0.f, 0.f, 0.f, 0.f); return; }

    const int l0 = g_start[b * 2050 + s];
    const int l1 = g_start[b * 2050 + s + 1];
    float4 acc = make_float4(0.f, 0.f, 0.f, 0.f);
    const float4* xp = (const float4*)(x + ((size_t)b * LL + l0) * DD) + tid;
    for (int l = l0; l < l1; ++l) {
        float4 v = *xp;
        acc.x += v.x; acc.y += v.y; acc.z += v.z; acc.w += v.w;
        xp += DD / 4;
    }
    const float inv = 1.0f / ((float)(l1 - l0) + 1e-9f);
    acc.x *= inv; acc.y *= inv; acc.z *= inv; acc.w *= inv;
    *op = acc;
}

// ---------------------------------------------------------------------
// Kernel 5: upsampled[b,l,:] = shortened[b, cumsum(l), :]   (scale == 1.0f exactly)
// ---------------------------------------------------------------------
__global__ void upsample_kernel(const float* __restrict__ outS,
                                float* __restrict__ outU) {
    const int b = blockIdx.y;
    const int l = blockIdx.x;
    const int tid = threadIdx.x;
    const int c = g_cum[b * LL + l];
    const float4* sp = (const float4*)(outS + ((size_t)b * SROWS + c) * DD) + tid;
    float4* up = (float4*)(outU + ((size_t)b * LL + l) * DD) + tid;
    *up = *sp;
}

// ---------------------------------------------------------------------
// Kernel 6: binomial consistency loss (scalar)
// ---------------------------------------------------------------------
__global__ void loss_kernel(float* __restrict__ outLoss) {
    if (threadIdx.x == 0) {
        const double Lf = 2048.0;
        const double lgL = lgamma(2049.0);
        const double lp = log(0.25);
        const double l1p = log(0.75);
        double s = 0.0;
        for (int b = 0; b < BB; ++b) {
            double k = (double)g_cum[b * LL + LL - 1];
            double logp = lgL - lgamma(k + 1.0) - lgamma(Lf - k + 1.0)
                        + k * lp + (Lf - k) * l1p;
            s += logp;
        }
        outLoss[0] = (float)(-(s / 8.0) / 2048.0);
    }
}

// ---------------------------------------------------------------------
extern "C" void kernel_launch(void* const* d_in, const int* in_sizes, int n_in,
                              void* d_out, int out_size) {
    (void)in_sizes; (void)n_in; (void)out_size;

    const float* x          = (const float*)d_in[0];
    const float* noise      = (const float*)d_in[1];
    const float* W1         = (const float*)d_in[2];
    const float* b1         = (const float*)d_in[3];
    const float* W2         = (const float*)d_in[4];
    const float* b2         = (const float*)d_in[5];
    const float* null_group = (const float*)d_in[6];

    float* out  = (float*)d_out;
    float* outS = out;                                     // [8, 2049, 1024]
    float* outU = outS + (size_t)BB * SROWS * DD;          // [8, 2048, 1024]
    float* outL = outU + (size_t)BB * LL * DD;             // scalar

    gemm_logits_kernel<<<dim3(TOK / 128, DD / 128), 256>>>(x, W1, b1, W2);
    boundary_kernel<<<TOK / 256, 256>>>(noise, b2);
    scan_kernel<<<BB, 256>>>();
    shortened_kernel<<<dim3(SROWS, BB), 256>>>(x, null_group, outS);
    upsample_kernel<<<dim3(LL, BB), 256>>>(outS, outU);
    loss_kernel<<<1, 32>>>(outL);
}